// round 13
// baseline (speedup 1.0000x reference)
#include <cuda_runtime.h>
#include <cuda_fp16.h>
#include <math.h>
#include <stdint.h>

#define B_   256
#define T_   512
#define IN_  19
#define H_   512
#define KT1  9         // layer-1 chunks: 1 input + 8 hidden
#define KT2  16        // layer-2 chunks: 8 h1 + 8 h2
#define IMG  8192      // 64x64 fp16 swizzled image bytes (64 rows x 128B)
#define NCTA 128
#define ABUF  8192                  // one A chunk
#define APIPE (3 * ABUF)            // 24 KB A pipeline
#define B1OFF APIPE                 // 9 x 8KB resident layer-1 weights
#define B2OFF (B1OFF + KT1 * IMG)   // 16 x 8KB resident layer-2 weights
#define SMEM_DYN (B2OFF + KT2 * IMG)   // 229376 B = 224 KB

// ---------------- static device scratch (no allocs allowed) ----------------
__device__ __align__(16) unsigned char g_Bim1[32][KT1][IMG];   // [jb][chunk]
__device__ __align__(16) unsigned char g_Bim2[32][KT2][IMG];
__device__ __align__(16) unsigned char g_Ain[T_][4][IMG];      // [t][mh]
__device__ __align__(16) unsigned char g_h1im[2][4][8][IMG];   // [slot][mh][jchunk]
__device__ __align__(16) unsigned char g_h2im[2][4][8][IMG];
__device__ float g_bias1[4 * H_], g_bias2[4 * H_];
__device__ float g_h2fin[B_][H_];
__device__ volatile unsigned g_count;      // global barrier (monotonic gen)
__device__ volatile unsigned g_gen;
__device__ volatile unsigned g_cnt4[4];    // per-mh barriers
__device__ volatile unsigned g_gen4[4];

// ---------------- helpers ---------------------------------------------------
__device__ __forceinline__ uint32_t swz_(uint32_t o) { return o ^ ((o >> 3) & 0x70); }

__device__ __forceinline__ __half2 tanh2_(__half2 x) {
    __half2 y;
    asm("tanh.approx.f16x2 %0, %1;" : "=r"(*(uint32_t*)&y) : "r"(*(const uint32_t*)&x));
    return y;
}
__device__ __forceinline__ __half2 sigm2_(__half2 x) {
    const __half2 hhalf = __float2half2_rn(0.5f);
    return __hfma2(tanh2_(__hmul2(x, hhalf)), hhalf, hhalf);
}

__device__ __forceinline__ uint32_t smem_u32_(const void* p) {
    uint32_t a;
    asm("{ .reg .u64 t; cvta.to.shared.u64 t, %1; cvt.u32.u64 %0, t; }" : "=r"(a) : "l"(p));
    return a;
}
__device__ __forceinline__ void ldsm4_(uint32_t* r, uint32_t a) {
    asm volatile("ldmatrix.sync.aligned.m8n8.x4.shared.b16 {%0,%1,%2,%3}, [%4];"
        : "=r"(r[0]), "=r"(r[1]), "=r"(r[2]), "=r"(r[3]) : "r"(a));
}
__device__ __forceinline__ void mma_(float* d, const uint32_t* a, const uint32_t* b) {
    asm volatile("mma.sync.aligned.m16n8k16.row.col.f32.f16.f16.f32 "
        "{%0,%1,%2,%3}, {%4,%5,%6,%7}, {%8,%9}, {%0,%1,%2,%3};"
        : "+f"(d[0]), "+f"(d[1]), "+f"(d[2]), "+f"(d[3])
        : "r"(a[0]), "r"(a[1]), "r"(a[2]), "r"(a[3]), "r"(b[0]), "r"(b[1]));
}
__device__ __forceinline__ void cpa_(uint32_t sa, const void* ga) {
    asm volatile("cp.async.cg.shared.global [%0], [%1], 16;" :: "r"(sa), "l"(ga));
}
__device__ __forceinline__ void pk8_(const float* v, uint32_t* out4) {
    #pragma unroll
    for (int q = 0; q < 4; q++) {
        unsigned short h0 = __half_as_ushort(__float2half_rn(v[2 * q]));
        unsigned short h1 = __half_as_ushort(__float2half_rn(v[2 * q + 1]));
        out4[q] = (uint32_t)h0 | ((uint32_t)h1 << 16);
    }
}

// ---- mbarrier + bulk-DMA (single-instruction 8KB chunk copy) ---------------
#define MBAR_INIT(a, n) asm volatile("mbarrier.init.shared.b64 [%0], %1;" :: "r"(a), "r"(n) : "memory")
#define MBAR_EXPECT(a, bytes) \
    asm volatile("mbarrier.arrive.expect_tx.shared.b64 _, [%0], %1;" :: "r"(a), "r"(bytes) : "memory")

__device__ __forceinline__ void bulk_cp_(uint32_t dst, const void* src, uint32_t bytes, uint32_t mbar) {
    asm volatile(
        "cp.async.bulk.shared::cluster.global.mbarrier::complete_tx::bytes [%0], [%1], %2, [%3];"
        :: "r"(dst), "l"(src), "r"(bytes), "r"(mbar) : "memory");
}
__device__ __forceinline__ void mbar_wait_(uint32_t mbar, uint32_t parity) {
    uint32_t done;
    asm volatile(
        "{\n\t.reg .pred p;\n\t"
        "mbarrier.try_wait.parity.acquire.cta.shared::cta.b64 p, [%1], %2;\n\t"
        "selp.b32 %0, 1, 0, p;\n\t}"
        : "=r"(done) : "r"(mbar), "r"(parity) : "memory");
    if (!done) {
        asm volatile(
            "{\n\t.reg .pred P1;\n\t"
            "WL_%=:\n\t"
            "mbarrier.try_wait.parity.acquire.cta.shared::cta.b64 P1, [%0], %1, 0x989680;\n\t"
            "@P1 bra.uni WD_%=;\n\t"
            "bra.uni WL_%=;\n\t"
            "WD_%=:\n\t}"
            :: "r"(mbar), "r"(parity) : "memory");
    }
}

// ---------------- barriers (monotonic gen, self-resetting count) -------------
__device__ __forceinline__ void bar_any_(volatile unsigned* cnt, volatile unsigned* gen,
                                         unsigned n) {
    __syncthreads();
    if (threadIdx.x == 0) {
        __threadfence();
        unsigned g = *gen;
        if (atomicAdd((unsigned*)cnt, 1u) == n - 1u) {
            *cnt = 0;
            __threadfence();
            *gen = g + 1u;
        } else {
            while (*gen == g) { }
        }
        __threadfence();
    }
    __syncthreads();
}

// ---------------- one chunk of MMA (A stream + resident B) -------------------
__device__ __forceinline__ void compute_chunk_(uint32_t abuf, uint32_t bimg,
                                               float acc[8][4], int l, int w)
{
    const uint32_t arow  = (uint32_t)(w * 16 + (l & 15));
    const uint32_t abyte = (uint32_t)(((l >> 4) & 1) * 16);
    const uint32_t brow0 = (uint32_t)(((l >> 4) & 1) * 8 + (l & 7));
    const uint32_t bbyte = (uint32_t)(((l >> 3) & 1) * 16);

    #pragma unroll
    for (int ks = 0; ks < 4; ks++) {
        uint32_t a4[4];
        ldsm4_(a4, abuf + swz_(arow * 128 + (uint32_t)ks * 32 + abyte));
        #pragma unroll
        for (int tp = 0; tp < 4; tp++) {
            uint32_t b4[4];
            ldsm4_(b4, bimg + swz_(((uint32_t)tp * 16 + brow0) * 128 + (uint32_t)ks * 32 + bbyte));
            mma_(acc[2 * tp],     a4, b4);
            mma_(acc[2 * tp + 1], a4, b4 + 2);
        }
    }
}

// ---------------- fused LSTM cell epilogue (f16x2 MUFU path) -----------------
__device__ __forceinline__ void epilogue_(float acc[8][4], float* cst, const float* sb,
    int layer, int t, int mh, int jb, int w, int l, bool lastw)
{
    unsigned char* hb0 = (layer ? g_h2im : g_h1im)[(t + 1) & 1][mh][jb >> 2];

    #pragma unroll
    for (int a = 0; a < 2; a++) {
        #pragma unroll
        for (int rh = 0; rh < 2; rh++) {
            int row = 16 * w + (l >> 2) + rh * 8;
            int jj0 = 8 * a + 2 * (l & 3);
            float pi0 = acc[a][rh * 2 + 0]     + sb[jj0];
            float pi1 = acc[a][rh * 2 + 1]     + sb[jj0 + 1];
            float pf0 = acc[a + 2][rh * 2 + 0] + sb[16 + jj0];
            float pf1 = acc[a + 2][rh * 2 + 1] + sb[16 + jj0 + 1];
            float pg0 = acc[a + 4][rh * 2 + 0] + sb[32 + jj0];
            float pg1 = acc[a + 4][rh * 2 + 1] + sb[32 + jj0 + 1];
            float po0 = acc[a + 6][rh * 2 + 0] + sb[48 + jj0];
            float po1 = acc[a + 6][rh * 2 + 1] + sb[48 + jj0 + 1];

            __half2 si2 = sigm2_(__floats2half2_rn(pi0, pi1));
            __half2 sf2 = sigm2_(__floats2half2_rn(pf0, pf1));
            __half2 tg2 = tanh2_(__floats2half2_rn(pg0, pg1));
            __half2 so2 = sigm2_(__floats2half2_rn(po0, po1));

            float2 si = __half22float2(si2);
            float2 sf = __half22float2(sf2);
            float2 tg = __half22float2(tg2);

            int ci = a * 4 + rh * 2;
            float c0 = sf.x * cst[ci]     + si.x * tg.x;
            float c1 = sf.y * cst[ci + 1] + si.y * tg.y;
            cst[ci] = c0;
            cst[ci + 1] = c1;

            __half2 tc2 = tanh2_(__floats2half2_rn(c0, c1));
            __half2 h2v = __hmul2(so2, tc2);

            uint32_t off = swz_((uint32_t)(row * 128 + ((jb & 3) * 16 + jj0) * 2));
            *(uint32_t*)(hb0 + off) = *(const uint32_t*)&h2v;
            if (lastw) {
                float2 hf = __half22float2(h2v);
                g_h2fin[mh * 64 + row][jb * 16 + jj0]     = hf.x;
                g_h2fin[mh * 64 + row][jb * 16 + jj0 + 1] = hf.y;
            }
        }
    }
}

// ---------------- THE kernel ------------------------------------------------
// 128 CTAs x 256 threads, 1/SM (224KB smem). Weights smem-resident; per
// interval only A streams (17 x 8KB): one cp.async.bulk DMA per chunk,
// completed via mbarrier. Parity: fcnt[3] monotonic per-slot fill counters,
// updated in lockstep by all threads; at consume time the latest fill of the
// chunk's slot IS the chunk itself (reuse distance 3), so parity =
// (fcnt[sl]-1)&1. Warps 0-3 = layer 1, warps 4-7 = layer 2.
__global__ void __launch_bounds__(256, 1) lstm_all(
    const float* __restrict__ input,
    const float* __restrict__ l1_Wx, const float* __restrict__ l1_bx,
    const float* __restrict__ l1_Wh, const float* __restrict__ l1_bh,
    const float* __restrict__ l2_Wx, const float* __restrict__ l2_bx,
    const float* __restrict__ l2_Wh, const float* __restrict__ l2_bh,
    const float* __restrict__ fc1_W, const float* __restrict__ fc1_b,
    const float* __restrict__ fc2_W, const float* __restrict__ fc2_b,
    const float* __restrict__ fc3_W, const float* __restrict__ fc3_b,
    float* __restrict__ out)
{
    extern __shared__ unsigned char dsm[];
    __shared__ float s_bias[2][64];
    __shared__ __align__(8) unsigned long long s_mbar[3];

    const int tid = threadIdx.x;
    const int g  = tid >> 7;          // 0: layer-1 warps, 1: layer-2 warps
    const int gt = tid & 127;
    const int l  = gt & 31;
    const int w  = gt >> 5;
    const int mh = blockIdx.x >> 5;   // 0..3
    const int jb = blockIdx.x & 31;   // 0..31
    const uint32_t bufu = smem_u32_(dsm);
    uint32_t mbar_a[3];
    mbar_a[0] = smem_u32_(&s_mbar[0]);
    mbar_a[1] = smem_u32_(&s_mbar[1]);
    mbar_a[2] = smem_u32_(&s_mbar[2]);

    if (tid == 0) {
        MBAR_INIT(mbar_a[0], 1u);
        MBAR_INIT(mbar_a[1], 1u);
        MBAR_INIT(mbar_a[2], 1u);
    }
    __syncthreads();

    // ================= prep phase (distributed across grid) =================
    {
        const int gi = blockIdx.x * 256 + tid;
        const int gs = NCTA * 256;

        for (int i = gi; i < 4 * H_; i += gs) {
            g_bias1[i] = l1_bx[i] + l1_bh[i];
            g_bias2[i] = l2_bx[i] + l2_bh[i];
        }
        {
            const int n16 = (4 * 8 * IMG) / 16;
            uint4 z = make_uint4(0, 0, 0, 0);
            uint4* p1 = (uint4*)&g_h1im[0][0][0][0];
            uint4* p2 = (uint4*)&g_h2im[0][0][0][0];
            for (int i = gi; i < n16; i += gs) { p1[i] = z; p2[i] = z; }
        }
        for (int e = gi; e < 32 * KT1 * 64 * 8; e += gs) {
            int k8 = e & 7, nrow = (e >> 3) & 63, c = (e >> 9) % KT1, jbx = (e >> 9) / KT1;
            int R = (nrow >> 4) * H_ + jbx * 16 + (nrow & 15);
            float v[8];
            #pragma unroll
            for (int q = 0; q < 8; q++) {
                int k = k8 * 8 + q;
                v[q] = (c == 0) ? ((k < IN_) ? l1_Wx[R * IN_ + k] : 0.0f)
                                : l1_Wh[R * H_ + (c - 1) * 64 + k];
            }
            uint32_t u4[4];
            pk8_(v, u4);
            *(uint4*)&g_Bim1[jbx][c][swz_((uint32_t)(nrow * 128 + k8 * 16))] =
                make_uint4(u4[0], u4[1], u4[2], u4[3]);
        }
        for (int e = gi; e < 32 * KT2 * 64 * 8; e += gs) {
            int k8 = e & 7, nrow = (e >> 3) & 63, c = (e >> 9) & 15, jbx = e >> 13;
            int R = (nrow >> 4) * H_ + jbx * 16 + (nrow & 15);
            float v[8];
            #pragma unroll
            for (int q = 0; q < 8; q++)
                v[q] = (c < 8) ? l2_Wx[R * H_ + c * 64 + k8 * 8 + q]
                               : l2_Wh[R * H_ + (c - 8) * 64 + k8 * 8 + q];
            uint32_t u4[4];
            pk8_(v, u4);
            *(uint4*)&g_Bim2[jbx][c][swz_((uint32_t)(nrow * 128 + k8 * 16))] =
                make_uint4(u4[0], u4[1], u4[2], u4[3]);
        }
        for (int e = gi; e < T_ * 4 * 64 * 8; e += gs) {
            int k8 = e & 7, r = (e >> 3) & 63, mhh = (e >> 9) & 3, t = e >> 11;
            int b = mhh * 64 + r;
            float v[8];
            #pragma unroll
            for (int q = 0; q < 8; q++) {
                int k = k8 * 8 + q;
                v[q] = (k < IN_) ? input[(size_t)b * (T_ * IN_) + t * IN_ + k] : 0.0f;
            }
            uint32_t u4[4];
            pk8_(v, u4);
            *(uint4*)&g_Ain[t][mhh][swz_((uint32_t)(r * 128 + k8 * 16))] =
                make_uint4(u4[0], u4[1], u4[2], u4[3]);
        }
    }
    bar_any_(&g_count, &g_gen, NCTA);   // prep visible everywhere

    // ---- load resident weights into smem (once per launch) ----
    {
        for (int img = 0; img < KT1 + KT2; img++) {
            const uint4* src = (img < KT1) ? (const uint4*)g_Bim1[jb][img]
                                           : (const uint4*)g_Bim2[jb][img - KT1];
            uint32_t dst = bufu + B1OFF + (uint32_t)img * IMG;
            cpa_(dst + (uint32_t)tid * 16,         src + tid);
            cpa_(dst + (uint32_t)(tid + 256) * 16, src + tid + 256);
        }
        asm volatile("cp.async.commit_group;" ::: "memory");
        asm volatile("cp.async.wait_group 0;" ::: "memory");
    }
    if (tid < 128) {
        int layer = tid >> 6, i = tid & 63;
        const float* bsrc = layer ? g_bias2 : g_bias1;
        s_bias[layer][i] = bsrc[(i >> 4) * H_ + jb * 16 + (i & 15)];
    }
    __syncthreads();

    // ================= persistent recurrence =================
    float cst[8];
    #pragma unroll
    for (int i = 0; i < 8; i++) cst[i] = 0.0f;   // g0: c1, g1: c2

    unsigned fcnt[3] = {0u, 0u, 0u};   // monotonic per-slot fill counters (lockstep)

    for (int s = 0; s <= T_; s++) {
        const bool hasL1 = (s < T_), hasL2 = (s >= 1);
        const int c0 = hasL1 ? 0 : 1;
        const int c1 = hasL2 ? 17 : 9;

        // A-chunk source for stream index i
        auto asrc = [&](int i) -> const void* {
            if (i == 0)      return (const void*)g_Ain[s][mh];
            else if (i < 9)  return (const void*)g_h1im[s & 1][mh][i - 1];
            else             return (const void*)g_h2im[(s - 1) & 1][mh][i - 9];
        };
        auto issue = [&](int i) {
            int sl = i % 3;
            if (tid == 0) {
                MBAR_EXPECT(mbar_a[sl], (uint32_t)ABUF);
                bulk_cp_(bufu + (uint32_t)sl * ABUF, asrc(i), (uint32_t)ABUF, mbar_a[sl]);
            }
            fcnt[sl]++;          // all threads, lockstep
        };

        // prologue: issue first two chunks (their slots were consumed last interval)
        issue(c0);
        issue(c0 + 1);

        float acc[8][4];
        for (int i = c0; i < c1; i++) {
            const int sl = i % 3;
            // latest fill of slot sl is chunk i itself -> parity (fcnt[sl]-1)&1
            mbar_wait_(mbar_a[sl], (fcnt[sl] - 1u) & 1u);
            __syncthreads();   // all threads done with chunk i-1; safe to refill its slot

            if (i + 2 < c1) issue(i + 2);

            const uint32_t abuf = bufu + (uint32_t)sl * ABUF;

            if (g == 0) {
                if (hasL1 && i < 9) {
                    if (i == c0) {
                        #pragma unroll
                        for (int nt = 0; nt < 8; nt++)
                            #pragma unroll
                            for (int r = 0; r < 4; r++) acc[nt][r] = 0.0f;
                    }
                    compute_chunk_(abuf, bufu + B1OFF + (uint32_t)i * IMG, acc, l, w);
                    if (i == 8)
                        epilogue_(acc, cst, s_bias[0], 0, s, mh, jb, w, l, false);
                }
            } else {
                if (hasL2 && i >= 1) {
                    if (i == 1) {
                        #pragma unroll
                        for (int nt = 0; nt < 8; nt++)
                            #pragma unroll
                            for (int r = 0; r < 4; r++) acc[nt][r] = 0.0f;
                    }
                    compute_chunk_(abuf, bufu + B2OFF + (uint32_t)(i - 1) * IMG, acc, l, w);
                    if (i == 16)
                        epilogue_(acc, cst, s_bias[1], 1, s - 1, mh, jb, w, l, (s - 1) == T_ - 1);
                }
            }
        }
        bar_any_(&g_cnt4[mh], &g_gen4[mh], 32);   // mh-scoped step barrier
    }

    bar_any_(&g_count, &g_gen, NCTA);   // all mh groups done -> head

    // ================= FC head (blocks 0..31, 8 batches each) ================
    if (blockIdx.x < 32) {
        float* hv = (float*)dsm;             // [8][512]
        float* o1 = hv + 8 * 512;            // [8][256]
        float* o2 = o1 + 8 * 256;            // [8][128]
        const int b0 = blockIdx.x * 8;

        for (int i = tid; i < 8 * 512; i += 256)
            hv[i] = g_h2fin[b0 + (i >> 9)][i & 511];
        __syncthreads();

        {
            float acc[8] = {};
            const float* wp = &fc1_W[tid * 512];
            for (int k = 0; k < 512; k++) {
                float wv = wp[k];
                #pragma unroll
                for (int q = 0; q < 8; q++) acc[q] += wv * hv[q * 512 + k];
            }
            float bb = fc1_b[tid];
            #pragma unroll
            for (int q = 0; q < 8; q++) o1[q * 256 + tid] = fmaxf(acc[q] + bb, 0.0f);
        }
        __syncthreads();

        if (tid < 128) {
            float acc[8] = {};
            const float* wp = &fc2_W[tid * 256];
            for (int k = 0; k < 256; k++) {
                float wv = wp[k];
                #pragma unroll
                for (int q = 0; q < 8; q++) acc[q] += wv * o1[q * 256 + k];
            }
            float bb = fc2_b[tid];
            #pragma unroll
            for (int q = 0; q < 8; q++) o2[q * 128 + tid] = fmaxf(acc[q] + bb, 0.0f);
        }
        __syncthreads();

        if (tid < 8) {
            float sacc = 0.0f;
            for (int k = 0; k < 128; k++) sacc += fc3_W[k] * o2[tid * 128 + k];
            out[b0 + tid] = sacc + fc3_b[0];
        }
    }
}

// ---------------- launch -----------------------------------------------------
extern "C" void kernel_launch(void* const* d_in, const int* in_sizes, int n_in,
                              void* d_out, int out_size)
{
    const float* input  = (const float*)d_in[0];
    const float* l1_Wx  = (const float*)d_in[1];
    const float* l1_bx  = (const float*)d_in[2];
    const float* l1_Wh  = (const float*)d_in[3];
    const float* l1_bh  = (const float*)d_in[4];
    const float* l2_Wx  = (const float*)d_in[5];
    const float* l2_bx  = (const float*)d_in[6];
    const float* l2_Wh  = (const float*)d_in[7];
    const float* l2_bh  = (const float*)d_in[8];
    const float* fc1_W  = (const float*)d_in[9];
    const float* fc1_b  = (const float*)d_in[10];
    const float* fc2_W  = (const float*)d_in[11];
    const float* fc2_b  = (const float*)d_in[12];
    const float* fc3_W  = (const float*)d_in[13];
    const float* fc3_b  = (const float*)d_in[14];

    cudaFuncSetAttribute(lstm_all,
                         cudaFuncAttributeMaxDynamicSharedMemorySize, SMEM_DYN);

    lstm_all<<<NCTA, 256, SMEM_DYN>>>(input,
        l1_Wx, l1_bx, l1_Wh, l1_bh, l2_Wx, l2_bx, l2_Wh, l2_bh,
        fc1_W, fc1_b, fc2_W, fc2_b, fc3_W, fc3_b, (float*)d_out);
}

// round 14
// speedup vs baseline: 1.2752x; 1.2752x over previous
#include <cuda_runtime.h>
#include <cuda_fp16.h>
#include <math.h>
#include <stdint.h>

#define B_   256
#define T_   512
#define IN_  19
#define H_   512
#define KT1  9         // layer-1 chunks: 1 input + 8 hidden
#define KT2  16        // layer-2 chunks: 8 h1 + 8 h2
#define IMG  8192      // 64x64 fp16 swizzled image bytes (64 rows x 128B)
#define NCTA 128
#define ABUF  8192                  // one A chunk
#define APIPE (3 * ABUF)            // 24 KB A pipeline
#define B1OFF APIPE                 // 9 x 8KB resident layer-1 weights
#define B2OFF (B1OFF + KT1 * IMG)   // 16 x 8KB resident layer-2 weights
#define SMEM_DYN (B2OFF + KT2 * IMG)   // 229376 B = 224 KB

// ---------------- static device scratch (no allocs allowed) ----------------
__device__ __align__(16) unsigned char g_Bim1[32][KT1][IMG];   // [jb][chunk]
__device__ __align__(16) unsigned char g_Bim2[32][KT2][IMG];
__device__ __align__(16) unsigned char g_Ain[T_][4][IMG];      // [t][mh]
__device__ __align__(16) unsigned char g_h1im[2][4][8][IMG];   // [slot][mh][jchunk]
__device__ __align__(16) unsigned char g_h2im[2][4][8][IMG];
__device__ float g_bias1[4 * H_], g_bias2[4 * H_];
__device__ float g_h2fin[B_][H_];
__device__ volatile unsigned g_count;      // global barrier (monotonic gen)
__device__ volatile unsigned g_gen;
__device__ volatile unsigned g_cnt4[4];    // per-mh barriers
__device__ volatile unsigned g_gen4[4];

// ---------------- helpers ---------------------------------------------------
__device__ __forceinline__ uint32_t swz_(uint32_t o) { return o ^ ((o >> 3) & 0x70); }

__device__ __forceinline__ __half2 tanh2_(__half2 x) {
    __half2 y;
    asm("tanh.approx.f16x2 %0, %1;" : "=r"(*(uint32_t*)&y) : "r"(*(const uint32_t*)&x));
    return y;
}
__device__ __forceinline__ __half2 sigm2_(__half2 x) {
    const __half2 hhalf = __float2half2_rn(0.5f);
    return __hfma2(tanh2_(__hmul2(x, hhalf)), hhalf, hhalf);
}

__device__ __forceinline__ uint32_t smem_u32_(const void* p) {
    uint32_t a;
    asm("{ .reg .u64 t; cvta.to.shared.u64 t, %1; cvt.u32.u64 %0, t; }" : "=r"(a) : "l"(p));
    return a;
}
__device__ __forceinline__ void ldsm4_(uint32_t* r, uint32_t a) {
    asm volatile("ldmatrix.sync.aligned.m8n8.x4.shared.b16 {%0,%1,%2,%3}, [%4];"
        : "=r"(r[0]), "=r"(r[1]), "=r"(r[2]), "=r"(r[3]) : "r"(a));
}
__device__ __forceinline__ void mma_(float* d, const uint32_t* a, const uint32_t* b) {
    asm volatile("mma.sync.aligned.m16n8k16.row.col.f32.f16.f16.f32 "
        "{%0,%1,%2,%3}, {%4,%5,%6,%7}, {%8,%9}, {%0,%1,%2,%3};"
        : "+f"(d[0]), "+f"(d[1]), "+f"(d[2]), "+f"(d[3])
        : "r"(a[0]), "r"(a[1]), "r"(a[2]), "r"(a[3]), "r"(b[0]), "r"(b[1]));
}
__device__ __forceinline__ void cpa_(uint32_t sa, const void* ga) {
    asm volatile("cp.async.cg.shared.global [%0], [%1], 16;" :: "r"(sa), "l"(ga));
}
__device__ __forceinline__ void pk8_(const float* v, uint32_t* out4) {
    #pragma unroll
    for (int q = 0; q < 4; q++) {
        unsigned short h0 = __half_as_ushort(__float2half_rn(v[2 * q]));
        unsigned short h1 = __half_as_ushort(__float2half_rn(v[2 * q + 1]));
        out4[q] = (uint32_t)h0 | ((uint32_t)h1 << 16);
    }
}

// ---------------- barriers (monotonic gen, self-resetting count) -------------
__device__ __forceinline__ void bar_any_(volatile unsigned* cnt, volatile unsigned* gen,
                                         unsigned n) {
    __syncthreads();
    if (threadIdx.x == 0) {
        __threadfence();
        unsigned g = *gen;
        if (atomicAdd((unsigned*)cnt, 1u) == n - 1u) {
            *cnt = 0;
            __threadfence();
            *gen = g + 1u;
        } else {
            while (*gen == g) { }
        }
        __threadfence();
    }
    __syncthreads();
}

// ---------------- fat compute: 32 rows x 64 cols, B frags shared over mt -----
__device__ __forceinline__ void compute_fat_(uint32_t abuf, uint32_t bimg,
    float acc[2][8][4], int l, int band, int nks)
{
    const uint32_t abyte = (uint32_t)(((l >> 4) & 1) * 16);
    const uint32_t brow0 = (uint32_t)(((l >> 4) & 1) * 8 + (l & 7));
    const uint32_t bbyte = (uint32_t)(((l >> 3) & 1) * 16);

    #pragma unroll
    for (int ks = 0; ks < 4; ks++) {
        if (ks >= nks) break;
        uint32_t b4[4][4];
        #pragma unroll
        for (int tp = 0; tp < 4; tp++)
            ldsm4_(b4[tp], bimg + swz_(((uint32_t)tp * 16 + brow0) * 128 + (uint32_t)ks * 32 + bbyte));
        #pragma unroll
        for (int mt = 0; mt < 2; mt++) {
            uint32_t arow = (uint32_t)(band * 32 + mt * 16 + (l & 15));
            uint32_t a4[4];
            ldsm4_(a4, abuf + swz_(arow * 128 + (uint32_t)ks * 32 + abyte));
            #pragma unroll
            for (int tp = 0; tp < 4; tp++) {
                mma_(acc[mt][2 * tp],     a4, b4[tp]);
                mma_(acc[mt][2 * tp + 1], a4, b4[tp] + 2);
            }
        }
    }
}

// ---------------- fused LSTM cell epilogue (f16x2 MUFU path) -----------------
// w = row-tile index 0..3 (rows 16w..16w+15)
__device__ __forceinline__ void epilogue_(float acc[8][4], float* cst, const float* sb,
    int layer, int t, int mh, int jb, int w, int l, bool lastw)
{
    unsigned char* hb0 = (layer ? g_h2im : g_h1im)[(t + 1) & 1][mh][jb >> 2];

    #pragma unroll
    for (int a = 0; a < 2; a++) {
        #pragma unroll
        for (int rh = 0; rh < 2; rh++) {
            int row = 16 * w + (l >> 2) + rh * 8;
            int jj0 = 8 * a + 2 * (l & 3);
            float pi0 = acc[a][rh * 2 + 0]     + sb[jj0];
            float pi1 = acc[a][rh * 2 + 1]     + sb[jj0 + 1];
            float pf0 = acc[a + 2][rh * 2 + 0] + sb[16 + jj0];
            float pf1 = acc[a + 2][rh * 2 + 1] + sb[16 + jj0 + 1];
            float pg0 = acc[a + 4][rh * 2 + 0] + sb[32 + jj0];
            float pg1 = acc[a + 4][rh * 2 + 1] + sb[32 + jj0 + 1];
            float po0 = acc[a + 6][rh * 2 + 0] + sb[48 + jj0];
            float po1 = acc[a + 6][rh * 2 + 1] + sb[48 + jj0 + 1];

            __half2 si2 = sigm2_(__floats2half2_rn(pi0, pi1));
            __half2 sf2 = sigm2_(__floats2half2_rn(pf0, pf1));
            __half2 tg2 = tanh2_(__floats2half2_rn(pg0, pg1));
            __half2 so2 = sigm2_(__floats2half2_rn(po0, po1));

            float2 si = __half22float2(si2);
            float2 sf = __half22float2(sf2);
            float2 tg = __half22float2(tg2);

            int ci = a * 4 + rh * 2;
            float c0 = sf.x * cst[ci]     + si.x * tg.x;
            float c1 = sf.y * cst[ci + 1] + si.y * tg.y;
            cst[ci] = c0;
            cst[ci + 1] = c1;

            __half2 tc2 = tanh2_(__floats2half2_rn(c0, c1));
            __half2 h2v = __hmul2(so2, tc2);

            uint32_t off = swz_((uint32_t)(row * 128 + ((jb & 3) * 16 + jj0) * 2));
            *(uint32_t*)(hb0 + off) = *(const uint32_t*)&h2v;
            if (lastw) {
                float2 hf = __half22float2(h2v);
                g_h2fin[mh * 64 + row][jb * 16 + jj0]     = hf.x;
                g_h2fin[mh * 64 + row][jb * 16 + jj0 + 1] = hf.y;
            }
        }
    }
}

// ---------------- THE kernel ------------------------------------------------
// 128 CTAs x 256 threads, 1/SM (224KB smem). Weights smem-resident; per
// interval only A streams (17 x 8KB chunks, 3-slot ring).
// Warp specialization:
//   warps 0-3 = COMPUTE: warp = (layer = w>>1, band = w&1), 32 rows x 64 cols,
//               B fragments shared across the two m16 row-tiles.
//   warps 4-7 = COPY: warp (4+2b+h) copies half h of band b's 4KB region via
//               LDGSTS, self-throttled with cp.async.wait_group.
// Per-band named barrier (id 1+band, 128 thr: 2 compute + 2 copy warps) is the
// ONLY sync in the chunk loop; the two bands run decoupled pipelines.
// Refill safety: copy issues chunk i+2 (slot (i-1)%3) after the iter-i bar,
// which compute warps reach only after finishing chunk i-1.
__global__ void __launch_bounds__(256, 1) lstm_all(
    const float* __restrict__ input,
    const float* __restrict__ l1_Wx, const float* __restrict__ l1_bx,
    const float* __restrict__ l1_Wh, const float* __restrict__ l1_bh,
    const float* __restrict__ l2_Wx, const float* __restrict__ l2_bx,
    const float* __restrict__ l2_Wh, const float* __restrict__ l2_bh,
    const float* __restrict__ fc1_W, const float* __restrict__ fc1_b,
    const float* __restrict__ fc2_W, const float* __restrict__ fc2_b,
    const float* __restrict__ fc3_W, const float* __restrict__ fc3_b,
    float* __restrict__ out)
{
    extern __shared__ unsigned char dsm[];
    __shared__ float s_bias[2][64];

    const int tid  = threadIdx.x;
    const int warp = tid >> 5;
    const int l    = tid & 31;
    const int mh   = blockIdx.x >> 5;   // 0..3
    const int jb   = blockIdx.x & 31;   // 0..31
    const uint32_t bufu = smem_u32_(dsm);

    const bool is_copy = (warp >= 4);
    const int band  = is_copy ? ((warp - 4) >> 1) : (warp & 1);   // 0..1
    const int half  = (warp - 4) & 1;                             // copy only
    const int layer = warp >> 1;                                  // compute: 0/1

    // ================= prep phase (distributed across grid) =================
    {
        const int gi = blockIdx.x * 256 + tid;
        const int gs = NCTA * 256;

        for (int i = gi; i < 4 * H_; i += gs) {
            g_bias1[i] = l1_bx[i] + l1_bh[i];
            g_bias2[i] = l2_bx[i] + l2_bh[i];
        }
        {
            const int n16 = (4 * 8 * IMG) / 16;
            uint4 z = make_uint4(0, 0, 0, 0);
            uint4* p1 = (uint4*)&g_h1im[0][0][0][0];
            uint4* p2 = (uint4*)&g_h2im[0][0][0][0];
            for (int i = gi; i < n16; i += gs) { p1[i] = z; p2[i] = z; }
        }
        for (int e = gi; e < 32 * KT1 * 64 * 8; e += gs) {
            int k8 = e & 7, nrow = (e >> 3) & 63, c = (e >> 9) % KT1, jbx = (e >> 9) / KT1;
            int R = (nrow >> 4) * H_ + jbx * 16 + (nrow & 15);
            float v[8];
            #pragma unroll
            for (int q = 0; q < 8; q++) {
                int k = k8 * 8 + q;
                v[q] = (c == 0) ? ((k < IN_) ? l1_Wx[R * IN_ + k] : 0.0f)
                                : l1_Wh[R * H_ + (c - 1) * 64 + k];
            }
            uint32_t u4[4];
            pk8_(v, u4);
            *(uint4*)&g_Bim1[jbx][c][swz_((uint32_t)(nrow * 128 + k8 * 16))] =
                make_uint4(u4[0], u4[1], u4[2], u4[3]);
        }
        for (int e = gi; e < 32 * KT2 * 64 * 8; e += gs) {
            int k8 = e & 7, nrow = (e >> 3) & 63, c = (e >> 9) & 15, jbx = e >> 13;
            int R = (nrow >> 4) * H_ + jbx * 16 + (nrow & 15);
            float v[8];
            #pragma unroll
            for (int q = 0; q < 8; q++)
                v[q] = (c < 8) ? l2_Wx[R * H_ + c * 64 + k8 * 8 + q]
                               : l2_Wh[R * H_ + (c - 8) * 64 + k8 * 8 + q];
            uint32_t u4[4];
            pk8_(v, u4);
            *(uint4*)&g_Bim2[jbx][c][swz_((uint32_t)(nrow * 128 + k8 * 16))] =
                make_uint4(u4[0], u4[1], u4[2], u4[3]);
        }
        for (int e = gi; e < T_ * 4 * 64 * 8; e += gs) {
            int k8 = e & 7, r = (e >> 3) & 63, mhh = (e >> 9) & 3, t = e >> 11;
            int b = mhh * 64 + r;
            float v[8];
            #pragma unroll
            for (int q = 0; q < 8; q++) {
                int k = k8 * 8 + q;
                v[q] = (k < IN_) ? input[(size_t)b * (T_ * IN_) + t * IN_ + k] : 0.0f;
            }
            uint32_t u4[4];
            pk8_(v, u4);
            *(uint4*)&g_Ain[t][mhh][swz_((uint32_t)(r * 128 + k8 * 16))] =
                make_uint4(u4[0], u4[1], u4[2], u4[3]);
        }
    }
    bar_any_(&g_count, &g_gen, NCTA);   // prep visible everywhere

    // ---- load resident weights into smem (once per launch) ----
    {
        for (int img = 0; img < KT1 + KT2; img++) {
            const uint4* src = (img < KT1) ? (const uint4*)g_Bim1[jb][img]
                                           : (const uint4*)g_Bim2[jb][img - KT1];
            uint32_t dst = bufu + B1OFF + (uint32_t)img * IMG;
            cpa_(dst + (uint32_t)tid * 16,         src + tid);
            cpa_(dst + (uint32_t)(tid + 256) * 16, src + tid + 256);
        }
        asm volatile("cp.async.commit_group;" ::: "memory");
        asm volatile("cp.async.wait_group 0;" ::: "memory");
    }
    if (tid < 128) {
        int ly = tid >> 6, i = tid & 63;
        const float* bsrc = ly ? g_bias2 : g_bias1;
        s_bias[ly][i] = bsrc[(i >> 4) * H_ + jb * 16 + (i & 15)];
    }
    __syncthreads();

    // ================= persistent recurrence =================
    float cst[16];
    #pragma unroll
    for (int i = 0; i < 16; i++) cst[i] = 0.0f;

    for (int s = 0; s <= T_; s++) {
        const bool hasL1 = (s < T_), hasL2 = (s >= 1);
        const int c0 = hasL1 ? 0 : 1;
        const int c1 = hasL2 ? 17 : 9;

        // A-chunk source for stream index i
        auto asrc = [&](int i) -> const unsigned char* {
            if (i == 0)      return g_Ain[s][mh];
            else if (i < 9)  return g_h1im[s & 1][mh][i - 1];
            else             return g_h2im[(s - 1) & 1][mh][i - 9];
        };

        if (is_copy) {
            // ---- copy warp: owns 2KB of band's 4KB region ----
            const uint32_t roff = (uint32_t)(band * 4096 + half * 2048 + l * 16);
            auto issue = [&](int i) {
                const unsigned char* src = asrc(i) + roff;
                uint32_t dst = bufu + (uint32_t)(i % 3) * ABUF + roff;
                #pragma unroll
                for (int q = 0; q < 4; q++)
                    cpa_(dst + (uint32_t)q * 512u, src + q * 512);
                asm volatile("cp.async.commit_group;" ::: "memory");
            };
            issue(c0);
            issue(c0 + 1);
            for (int i = c0; i < c1; i++) {
                if (i < c1 - 1) asm volatile("cp.async.wait_group 1;" ::: "memory");
                else            asm volatile("cp.async.wait_group 0;" ::: "memory");
                asm volatile("bar.sync %0, 128;" :: "r"(1 + band) : "memory");
                if (i + 2 < c1) issue(i + 2);
            }
        } else {
            // ---- compute warp: layer (w>>1), band (w&1), 32 rows x 64 cols ----
            float acc[2][8][4];
            for (int i = c0; i < c1; i++) {
                asm volatile("bar.sync %0, 128;" :: "r"(1 + band) : "memory");
                const uint32_t abuf = bufu + (uint32_t)(i % 3) * ABUF;

                if (layer == 0) {
                    if (hasL1 && i < 9) {
                        if (i == c0) {
                            #pragma unroll
                            for (int mt = 0; mt < 2; mt++)
                                #pragma unroll
                                for (int nt = 0; nt < 8; nt++)
                                    #pragma unroll
                                    for (int r = 0; r < 4; r++) acc[mt][nt][r] = 0.0f;
                        }
                        compute_fat_(abuf, bufu + B1OFF + (uint32_t)i * IMG, acc, l, band,
                                     (i == 0) ? 2 : 4);
                        if (i == 8) {
                            #pragma unroll
                            for (int mt = 0; mt < 2; mt++)
                                epilogue_(acc[mt], cst + 8 * mt, s_bias[0], 0, s, mh, jb,
                                          2 * band + mt, l, false);
                        }
                    }
                } else {
                    if (hasL2 && i >= 1) {
                        if (i == 1) {
                            #pragma unroll
                            for (int mt = 0; mt < 2; mt++)
                                #pragma unroll
                                for (int nt = 0; nt < 8; nt++)
                                    #pragma unroll
                                    for (int r = 0; r < 4; r++) acc[mt][nt][r] = 0.0f;
                        }
                        compute_fat_(abuf, bufu + B2OFF + (uint32_t)(i - 1) * IMG, acc, l, band, 4);
                        if (i == 16) {
                            #pragma unroll
                            for (int mt = 0; mt < 2; mt++)
                                epilogue_(acc[mt], cst + 8 * mt, s_bias[1], 1, s - 1, mh, jb,
                                          2 * band + mt, l, (s - 1) == T_ - 1);
                        }
                    }
                }
            }
        }
        bar_any_(&g_cnt4[mh], &g_gen4[mh], 32);   // mh-scoped step barrier
    }

    bar_any_(&g_count, &g_gen, NCTA);   // all mh groups done -> head

    // ================= FC head (blocks 0..31, 8 batches each) ================
    if (blockIdx.x < 32) {
        float* hv = (float*)dsm;             // [8][512]
        float* o1 = hv + 8 * 512;            // [8][256]
        float* o2 = o1 + 8 * 256;            // [8][128]
        const int b0 = blockIdx.x * 8;

        for (int i = tid; i < 8 * 512; i += 256)
            hv[i] = g_h2fin[b0 + (i >> 9)][i & 511];
        __syncthreads();

        {
            float acc[8] = {};
            const float* wp = &fc1_W[tid * 512];
            for (int k = 0; k < 512; k++) {
                float wv = wp[k];
                #pragma unroll
                for (int q = 0; q < 8; q++) acc[q] += wv * hv[q * 512 + k];
            }
            float bb = fc1_b[tid];
            #pragma unroll
            for (int q = 0; q < 8; q++) o1[q * 256 + tid] = fmaxf(acc[q] + bb, 0.0f);
        }
        __syncthreads();

        if (tid < 128) {
            float acc[8] = {};
            const float* wp = &fc2_W[tid * 256];
            for (int k = 0; k < 256; k++) {
                float wv = wp[k];
                #pragma unroll
                for (int q = 0; q < 8; q++) acc[q] += wv * o1[q * 256 + k];
            }
            float bb = fc2_b[tid];
            #pragma unroll
            for (int q = 0; q < 8; q++) o2[q * 128 + tid] = fmaxf(acc[q] + bb, 0.0f);
        }
        __syncthreads();

        if (tid < 8) {
            float sacc = 0.0f;
            for (int k = 0; k < 128; k++) sacc += fc3_W[k] * o2[tid * 128 + k];
            out[b0 + tid] = sacc + fc3_b[0];
        }
    }
}

// ---------------- launch -----------------------------------------------------
extern "C" void kernel_launch(void* const* d_in, const int* in_sizes, int n_in,
                              void* d_out, int out_size)
{
    const float* input  = (const float*)d_in[0];
    const float* l1_Wx  = (const float*)d_in[1];
    const float* l1_bx  = (const float*)d_in[2];
    const float* l1_Wh  = (const float*)d_in[3];
    const float* l1_bh  = (const float*)d_in[4];
    const float* l2_Wx  = (const float*)d_in[5];
    const float* l2_bx  = (const float*)d_in[6];
    const float* l2_Wh  = (const float*)d_in[7];
    const float* l2_bh  = (const float*)d_in[8];
    const float* fc1_W  = (const float*)d_in[9];
    const float* fc1_b  = (const float*)d_in[10];
    const float* fc2_W  = (const float*)d_in[11];
    const float* fc2_b  = (const float*)d_in[12];
    const float* fc3_W  = (const float*)d_in[13];
    const float* fc3_b  = (const float*)d_in[14];

    cudaFuncSetAttribute(lstm_all,
                         cudaFuncAttributeMaxDynamicSharedMemorySize, SMEM_DYN);

    lstm_all<<<NCTA, 256, SMEM_DYN>>>(input,
        l1_Wx, l1_bx, l1_Wh, l1_bh, l2_Wx, l2_bx, l2_Wh, l2_bh,
        fc1_W, fc1_b, fc2_W, fc2_b, fc3_W, fc3_b, (float*)d_out);
}

// round 15
// speedup vs baseline: 1.3797x; 1.0820x over previous
#include <cuda_runtime.h>
#include <cuda_fp16.h>
#include <math.h>
#include <stdint.h>

#define B_   256
#define T_   512
#define IN_  19
#define H_   512
#define KT1  9         // layer-1 chunks: 1 input + 8 hidden
#define KT2  16        // layer-2 chunks: 8 h1 + 8 h2
#define IMG  8192      // 64x64 fp16 swizzled image bytes (64 rows x 128B)
#define NCTA 128
#define ABUF  8192                  // one A chunk
#define APIPE (3 * ABUF)            // 24 KB A pipeline
#define B1OFF APIPE                 // 9 x 8KB resident layer-1 weights
#define B2OFF (B1OFF + KT1 * IMG)   // 16 x 8KB resident layer-2 weights
#define SMEM_DYN (B2OFF + KT2 * IMG)   // 229376 B = 224 KB

// ---------------- static device scratch (no allocs allowed) ----------------
__device__ __align__(16) unsigned char g_Bim1[32][KT1][IMG];   // [jb][chunk]
__device__ __align__(16) unsigned char g_Bim2[32][KT2][IMG];
__device__ __align__(16) unsigned char g_Ain[T_][4][IMG];      // [t][mh]
__device__ __align__(16) unsigned char g_h1im[2][4][8][IMG];   // [slot][mh][jchunk]
__device__ __align__(16) unsigned char g_h2im[2][4][8][IMG];
__device__ float g_bias1[4 * H_], g_bias2[4 * H_];
__device__ float g_h2fin[B_][H_];
__device__ volatile unsigned g_count;      // global barrier (monotonic gen)
__device__ volatile unsigned g_gen;
__device__ volatile unsigned g_c1[4][2];   // [mh][band] L1-epilogue arrivals (monotonic)
__device__ volatile unsigned g_c2[4][2];   // [mh][band] L2-epilogue arrivals (monotonic)

// ---------------- helpers ---------------------------------------------------
__device__ __forceinline__ uint32_t swz_(uint32_t o) { return o ^ ((o >> 3) & 0x70); }

__device__ __forceinline__ __half2 tanh2_(__half2 x) {
    __half2 y;
    asm("tanh.approx.f16x2 %0, %1;" : "=r"(*(uint32_t*)&y) : "r"(*(const uint32_t*)&x));
    return y;
}
__device__ __forceinline__ __half2 sigm2_(__half2 x) {
    const __half2 hhalf = __float2half2_rn(0.5f);
    return __hfma2(tanh2_(__hmul2(x, hhalf)), hhalf, hhalf);
}

__device__ __forceinline__ uint32_t smem_u32_(const void* p) {
    uint32_t a;
    asm("{ .reg .u64 t; cvta.to.shared.u64 t, %1; cvt.u32.u64 %0, t; }" : "=r"(a) : "l"(p));
    return a;
}
__device__ __forceinline__ void ldsm4_(uint32_t* r, uint32_t a) {
    asm volatile("ldmatrix.sync.aligned.m8n8.x4.shared.b16 {%0,%1,%2,%3}, [%4];"
        : "=r"(r[0]), "=r"(r[1]), "=r"(r[2]), "=r"(r[3]) : "r"(a));
}
__device__ __forceinline__ void mma_(float* d, const uint32_t* a, const uint32_t* b) {
    asm volatile("mma.sync.aligned.m16n8k16.row.col.f32.f16.f16.f32 "
        "{%0,%1,%2,%3}, {%4,%5,%6,%7}, {%8,%9}, {%0,%1,%2,%3};"
        : "+f"(d[0]), "+f"(d[1]), "+f"(d[2]), "+f"(d[3])
        : "r"(a[0]), "r"(a[1]), "r"(a[2]), "r"(a[3]), "r"(b[0]), "r"(b[1]));
}
__device__ __forceinline__ void cpa_(uint32_t sa, const void* ga) {
    asm volatile("cp.async.cg.shared.global [%0], [%1], 16;" :: "r"(sa), "l"(ga));
}
__device__ __forceinline__ void pk8_(const float* v, uint32_t* out4) {
    #pragma unroll
    for (int q = 0; q < 4; q++) {
        unsigned short h0 = __half_as_ushort(__float2half_rn(v[2 * q]));
        unsigned short h1 = __half_as_ushort(__float2half_rn(v[2 * q + 1]));
        out4[q] = (uint32_t)h0 | ((uint32_t)h1 << 16);
    }
}

// ---------------- barriers ---------------------------------------------------
__device__ __forceinline__ void bar_any_(volatile unsigned* cnt, volatile unsigned* gen,
                                         unsigned n) {
    __syncthreads();
    if (threadIdx.x == 0) {
        __threadfence();
        unsigned g = *gen;
        if (atomicAdd((unsigned*)cnt, 1u) == n - 1u) {
            *cnt = 0;
            __threadfence();
            *gen = g + 1u;
        } else {
            while (*gen == g) { }
        }
        __threadfence();
    }
    __syncthreads();
}

// spin until monotonic counter reaches target, then acquire-fence
__device__ __forceinline__ void wait_cnt_(volatile unsigned* c, unsigned tgt) {
    while (*c < tgt) { }
    __threadfence();
}

// ---------------- fat compute: 32 rows x 64 cols, B frags shared over mt -----
__device__ __forceinline__ void compute_fat_(uint32_t abuf, uint32_t bimg,
    float acc[2][8][4], int l, int band, int nks)
{
    const uint32_t abyte = (uint32_t)(((l >> 4) & 1) * 16);
    const uint32_t brow0 = (uint32_t)(((l >> 4) & 1) * 8 + (l & 7));
    const uint32_t bbyte = (uint32_t)(((l >> 3) & 1) * 16);

    #pragma unroll
    for (int ks = 0; ks < 4; ks++) {
        if (ks >= nks) break;
        uint32_t b4[4][4];
        #pragma unroll
        for (int tp = 0; tp < 4; tp++)
            ldsm4_(b4[tp], bimg + swz_(((uint32_t)tp * 16 + brow0) * 128 + (uint32_t)ks * 32 + bbyte));
        #pragma unroll
        for (int mt = 0; mt < 2; mt++) {
            uint32_t arow = (uint32_t)(band * 32 + mt * 16 + (l & 15));
            uint32_t a4[4];
            ldsm4_(a4, abuf + swz_(arow * 128 + (uint32_t)ks * 32 + abyte));
            #pragma unroll
            for (int tp = 0; tp < 4; tp++) {
                mma_(acc[mt][2 * tp],     a4, b4[tp]);
                mma_(acc[mt][2 * tp + 1], a4, b4[tp] + 2);
            }
        }
    }
}

// ---------------- fused LSTM cell epilogue (f16x2 MUFU path) -----------------
__device__ __forceinline__ void epilogue_(float acc[8][4], float* cst, const float* sb,
    int layer, int t, int mh, int jb, int w, int l, bool lastw)
{
    unsigned char* hb0 = (layer ? g_h2im : g_h1im)[(t + 1) & 1][mh][jb >> 2];

    #pragma unroll
    for (int a = 0; a < 2; a++) {
        #pragma unroll
        for (int rh = 0; rh < 2; rh++) {
            int row = 16 * w + (l >> 2) + rh * 8;
            int jj0 = 8 * a + 2 * (l & 3);
            float pi0 = acc[a][rh * 2 + 0]     + sb[jj0];
            float pi1 = acc[a][rh * 2 + 1]     + sb[jj0 + 1];
            float pf0 = acc[a + 2][rh * 2 + 0] + sb[16 + jj0];
            float pf1 = acc[a + 2][rh * 2 + 1] + sb[16 + jj0 + 1];
            float pg0 = acc[a + 4][rh * 2 + 0] + sb[32 + jj0];
            float pg1 = acc[a + 4][rh * 2 + 1] + sb[32 + jj0 + 1];
            float po0 = acc[a + 6][rh * 2 + 0] + sb[48 + jj0];
            float po1 = acc[a + 6][rh * 2 + 1] + sb[48 + jj0 + 1];

            __half2 si2 = sigm2_(__floats2half2_rn(pi0, pi1));
            __half2 sf2 = sigm2_(__floats2half2_rn(pf0, pf1));
            __half2 tg2 = tanh2_(__floats2half2_rn(pg0, pg1));
            __half2 so2 = sigm2_(__floats2half2_rn(po0, po1));

            float2 si = __half22float2(si2);
            float2 sf = __half22float2(sf2);
            float2 tg = __half22float2(tg2);

            int ci = a * 4 + rh * 2;
            float c0 = sf.x * cst[ci]     + si.x * tg.x;
            float c1 = sf.y * cst[ci + 1] + si.y * tg.y;
            cst[ci] = c0;
            cst[ci + 1] = c1;

            __half2 tc2 = tanh2_(__floats2half2_rn(c0, c1));
            __half2 h2v = __hmul2(so2, tc2);

            uint32_t off = swz_((uint32_t)(row * 128 + ((jb & 3) * 16 + jj0) * 2));
            *(uint32_t*)(hb0 + off) = *(const uint32_t*)&h2v;
            if (lastw) {
                float2 hf = __half22float2(h2v);
                g_h2fin[mh * 64 + row][jb * 16 + jj0]     = hf.x;
                g_h2fin[mh * 64 + row][jb * 16 + jj0 + 1] = hf.y;
            }
        }
    }
}

// ---------------- THE kernel ------------------------------------------------
// 128 CTAs x 256 threads, 1/SM (224KB smem). Weights smem-resident; A streams
// 17 x 8KB chunks (3-slot ring). Warp roles as round 14 (4 fat compute +
// 4 copy). NO per-interval hard barrier: bands (rows 0-31 / 32-63) are fully
// independent; producer/consumer ordering runs on monotonic per-(mh,band)
// counters with arrive-early (at epilogue) / wait-late (at first h1/h2 copy
// issue) placement. Drift is bounded to 1 interval, matching the 2-slot
// ping-pong; cnt arrivals certify both "produced h[s]" and "done reading
// h[s-1]" (arrival is after the warp's last read+write of the interval).
__global__ void __launch_bounds__(256, 1) lstm_all(
    const float* __restrict__ input,
    const float* __restrict__ l1_Wx, const float* __restrict__ l1_bx,
    const float* __restrict__ l1_Wh, const float* __restrict__ l1_bh,
    const float* __restrict__ l2_Wx, const float* __restrict__ l2_bx,
    const float* __restrict__ l2_Wh, const float* __restrict__ l2_bh,
    const float* __restrict__ fc1_W, const float* __restrict__ fc1_b,
    const float* __restrict__ fc2_W, const float* __restrict__ fc2_b,
    const float* __restrict__ fc3_W, const float* __restrict__ fc3_b,
    float* __restrict__ out)
{
    extern __shared__ unsigned char dsm[];
    __shared__ float s_bias[2][64];

    const int tid  = threadIdx.x;
    const int warp = tid >> 5;
    const int l    = tid & 31;
    const int mh   = blockIdx.x >> 5;   // 0..3
    const int jb   = blockIdx.x & 31;   // 0..31
    const uint32_t bufu = smem_u32_(dsm);

    const bool is_copy = (warp >= 4);
    const int band  = is_copy ? ((warp - 4) >> 1) : (warp & 1);   // 0..1
    const int half  = (warp - 4) & 1;                             // copy only
    const int layer = warp >> 1;                                  // compute: 0/1

    // ================= prep phase (distributed across grid) =================
    {
        const int gi = blockIdx.x * 256 + tid;
        const int gs = NCTA * 256;

        if (blockIdx.x == 0 && tid < 16) {   // reset flow counters each launch
            if (tid < 8) ((volatile unsigned*)g_c1)[tid] = 0u;
            else         ((volatile unsigned*)g_c2)[tid - 8] = 0u;
        }

        for (int i = gi; i < 4 * H_; i += gs) {
            g_bias1[i] = l1_bx[i] + l1_bh[i];
            g_bias2[i] = l2_bx[i] + l2_bh[i];
        }
        {
            const int n16 = (4 * 8 * IMG) / 16;
            uint4 z = make_uint4(0, 0, 0, 0);
            uint4* p1 = (uint4*)&g_h1im[0][0][0][0];
            uint4* p2 = (uint4*)&g_h2im[0][0][0][0];
            for (int i = gi; i < n16; i += gs) { p1[i] = z; p2[i] = z; }
        }
        for (int e = gi; e < 32 * KT1 * 64 * 8; e += gs) {
            int k8 = e & 7, nrow = (e >> 3) & 63, c = (e >> 9) % KT1, jbx = (e >> 9) / KT1;
            int R = (nrow >> 4) * H_ + jbx * 16 + (nrow & 15);
            float v[8];
            #pragma unroll
            for (int q = 0; q < 8; q++) {
                int k = k8 * 8 + q;
                v[q] = (c == 0) ? ((k < IN_) ? l1_Wx[R * IN_ + k] : 0.0f)
                                : l1_Wh[R * H_ + (c - 1) * 64 + k];
            }
            uint32_t u4[4];
            pk8_(v, u4);
            *(uint4*)&g_Bim1[jbx][c][swz_((uint32_t)(nrow * 128 + k8 * 16))] =
                make_uint4(u4[0], u4[1], u4[2], u4[3]);
        }
        for (int e = gi; e < 32 * KT2 * 64 * 8; e += gs) {
            int k8 = e & 7, nrow = (e >> 3) & 63, c = (e >> 9) & 15, jbx = e >> 13;
            int R = (nrow >> 4) * H_ + jbx * 16 + (nrow & 15);
            float v[8];
            #pragma unroll
            for (int q = 0; q < 8; q++)
                v[q] = (c < 8) ? l2_Wx[R * H_ + c * 64 + k8 * 8 + q]
                               : l2_Wh[R * H_ + (c - 8) * 64 + k8 * 8 + q];
            uint32_t u4[4];
            pk8_(v, u4);
            *(uint4*)&g_Bim2[jbx][c][swz_((uint32_t)(nrow * 128 + k8 * 16))] =
                make_uint4(u4[0], u4[1], u4[2], u4[3]);
        }
        for (int e = gi; e < T_ * 4 * 64 * 8; e += gs) {
            int k8 = e & 7, r = (e >> 3) & 63, mhh = (e >> 9) & 3, t = e >> 11;
            int b = mhh * 64 + r;
            float v[8];
            #pragma unroll
            for (int q = 0; q < 8; q++) {
                int k = k8 * 8 + q;
                v[q] = (k < IN_) ? input[(size_t)b * (T_ * IN_) + t * IN_ + k] : 0.0f;
            }
            uint32_t u4[4];
            pk8_(v, u4);
            *(uint4*)&g_Ain[t][mhh][swz_((uint32_t)(r * 128 + k8 * 16))] =
                make_uint4(u4[0], u4[1], u4[2], u4[3]);
        }
    }
    bar_any_(&g_count, &g_gen, NCTA);   // prep + counter reset visible everywhere

    // ---- load resident weights into smem (once per launch) ----
    {
        for (int img = 0; img < KT1 + KT2; img++) {
            const uint4* src = (img < KT1) ? (const uint4*)g_Bim1[jb][img]
                                           : (const uint4*)g_Bim2[jb][img - KT1];
            uint32_t dst = bufu + B1OFF + (uint32_t)img * IMG;
            cpa_(dst + (uint32_t)tid * 16,         src + tid);
            cpa_(dst + (uint32_t)(tid + 256) * 16, src + tid + 256);
        }
        asm volatile("cp.async.commit_group;" ::: "memory");
        asm volatile("cp.async.wait_group 0;" ::: "memory");
    }
    if (tid < 128) {
        int ly = tid >> 6, i = tid & 63;
        const float* bsrc = ly ? g_bias2 : g_bias1;
        s_bias[ly][i] = bsrc[(i >> 4) * H_ + jb * 16 + (i & 15)];
    }
    __syncthreads();

    // ================= persistent recurrence =================
    float cst[16];
    #pragma unroll
    for (int i = 0; i < 16; i++) cst[i] = 0.0f;

    for (int s = 0; s <= T_; s++) {
        const bool hasL1 = (s < T_), hasL2 = (s >= 1);
        const int c0 = hasL1 ? 0 : 1;
        const int c1 = hasL2 ? 17 : 9;

        // A-chunk source for stream index i
        auto asrc = [&](int i) -> const unsigned char* {
            if (i == 0)      return g_Ain[s][mh];
            else if (i < 9)  return g_h1im[s & 1][mh][i - 1];
            else             return g_h2im[(s - 1) & 1][mh][i - 9];
        };

        if (is_copy) {
            // ---- copy warp: owns 2KB of band's 4KB region ----
            const uint32_t roff = (uint32_t)(band * 4096 + half * 2048 + l * 16);
            auto issue = [&](int i) {
                const unsigned char* src = asrc(i) + roff;
                uint32_t dst = bufu + (uint32_t)(i % 3) * ABUF + roff;
                #pragma unroll
                for (int q = 0; q < 4; q++)
                    cpa_(dst + (uint32_t)q * 512u, src + q * 512);
                asm volatile("cp.async.commit_group;" ::: "memory");
            };
            // prologue: chunk 0 (input) needs nothing; h1 chunks gated by cnt1
            if (c0 == 0) {
                issue(0);
                wait_cnt_(&g_c1[mh][band], 32u * (unsigned)s);
                issue(1);
            } else {   // s == T_: streams start at 1 (h1)
                wait_cnt_(&g_c1[mh][band], 32u * (unsigned)s);
                issue(1);
                issue(2);
            }
            for (int i = c0; i < c1; i++) {
                if (i < c1 - 1) asm volatile("cp.async.wait_group 1;" ::: "memory");
                else            asm volatile("cp.async.wait_group 0;" ::: "memory");
                asm volatile("bar.sync %0, 128;" :: "r"(1 + band) : "memory");
                if (i + 2 < c1) {
                    if (i + 2 == 9)   // first h2 stream: gate on L2 producers
                        wait_cnt_(&g_c2[mh][band], 32u * (unsigned)(s - 1));
                    issue(i + 2);
                }
            }
        } else {
            // ---- compute warp: layer (w>>1), band (w&1), 32 rows x 64 cols ----
            float acc[2][8][4];
            for (int i = c0; i < c1; i++) {
                asm volatile("bar.sync %0, 128;" :: "r"(1 + band) : "memory");
                const uint32_t abuf = bufu + (uint32_t)(i % 3) * ABUF;

                if (layer == 0) {
                    if (hasL1 && i < 9) {
                        if (i == c0) {
                            #pragma unroll
                            for (int mt = 0; mt < 2; mt++)
                                #pragma unroll
                                for (int nt = 0; nt < 8; nt++)
                                    #pragma unroll
                                    for (int r = 0; r < 4; r++) acc[mt][nt][r] = 0.0f;
                        }
                        compute_fat_(abuf, bufu + B1OFF + (uint32_t)i * IMG, acc, l, band,
                                     (i == 0) ? 2 : 4);
                        if (i == 8) {
                            #pragma unroll
                            for (int mt = 0; mt < 2; mt++)
                                epilogue_(acc[mt], cst + 8 * mt, s_bias[0], 0, s, mh, jb,
                                          2 * band + mt, l, false);
                            __threadfence();
                            __syncwarp();
                            if (l == 0) atomicAdd((unsigned*)&g_c1[mh][band], 1u);
                        }
                    }
                } else {
                    if (hasL2 && i >= 1) {
                        if (i == 1) {
                            #pragma unroll
                            for (int mt = 0; mt < 2; mt++)
                                #pragma unroll
                                for (int nt = 0; nt < 8; nt++)
                                    #pragma unroll
                                    for (int r = 0; r < 4; r++) acc[mt][nt][r] = 0.0f;
                        }
                        compute_fat_(abuf, bufu + B2OFF + (uint32_t)(i - 1) * IMG, acc, l, band, 4);
                        if (i == 16) {
                            #pragma unroll
                            for (int mt = 0; mt < 2; mt++)
                                epilogue_(acc[mt], cst + 8 * mt, s_bias[1], 1, s - 1, mh, jb,
                                          2 * band + mt, l, (s - 1) == T_ - 1);
                            __threadfence();
                            __syncwarp();
                            if (l == 0) atomicAdd((unsigned*)&g_c2[mh][band], 1u);
                        }
                    }
                }
            }
        }
    }

    bar_any_(&g_count, &g_gen, NCTA);   // all flows done -> head

    // ================= FC head (blocks 0..31, 8 batches each) ================
    if (blockIdx.x < 32) {
        float* hv = (float*)dsm;             // [8][512]
        float* o1 = hv + 8 * 512;            // [8][256]
        float* o2 = o1 + 8 * 256;            // [8][128]
        const int b0 = blockIdx.x * 8;

        for (int i = tid; i < 8 * 512; i += 256)
            hv[i] = g_h2fin[b0 + (i >> 9)][i & 511];
        __syncthreads();

        {
            float acc[8] = {};
            const float* wp = &fc1_W[tid * 512];
            for (int k = 0; k < 512; k++) {
                float wv = wp[k];
                #pragma unroll
                for (int q = 0; q < 8; q++) acc[q] += wv * hv[q * 512 + k];
            }
            float bb = fc1_b[tid];
            #pragma unroll
            for (int q = 0; q < 8; q++) o1[q * 256 + tid] = fmaxf(acc[q] + bb, 0.0f);
        }
        __syncthreads();

        if (tid < 128) {
            float acc[8] = {};
            const float* wp = &fc2_W[tid * 256];
            for (int k = 0; k < 256; k++) {
                float wv = wp[k];
                #pragma unroll
                for (int q = 0; q < 8; q++) acc[q] += wv * o1[q * 256 + k];
            }
            float bb = fc2_b[tid];
            #pragma unroll
            for (int q = 0; q < 8; q++) o2[q * 128 + tid] = fmaxf(acc[q] + bb, 0.0f);
        }
        __syncthreads();

        if (tid < 8) {
            float sacc = 0.0f;
            for (int k = 0; k < 128; k++) sacc += fc3_W[k] * o2[tid * 128 + k];
            out[b0 + tid] = sacc + fc3_b[0];
        }
    }
}

// ---------------- launch -----------------------------------------------------
extern "C" void kernel_launch(void* const* d_in, const int* in_sizes, int n_in,
                              void* d_out, int out_size)
{
    const float* input  = (const float*)d_in[0];
    const float* l1_Wx  = (const float*)d_in[1];
    const float* l1_bx  = (const float*)d_in[2];
    const float* l1_Wh  = (const float*)d_in[3];
    const float* l1_bh  = (const float*)d_in[4];
    const float* l2_Wx  = (const float*)d_in[5];
    const float* l2_bx  = (const float*)d_in[6];
    const float* l2_Wh  = (const float*)d_in[7];
    const float* l2_bh  = (const float*)d_in[8];
    const float* fc1_W  = (const float*)d_in[9];
    const float* fc1_b  = (const float*)d_in[10];
    const float* fc2_W  = (const float*)d_in[11];
    const float* fc2_b  = (const float*)d_in[12];
    const float* fc3_W  = (const float*)d_in[13];
    const float* fc3_b  = (const float*)d_in[14];

    cudaFuncSetAttribute(lstm_all,
                         cudaFuncAttributeMaxDynamicSharedMemorySize, SMEM_DYN);

    lstm_all<<<NCTA, 256, SMEM_DYN>>>(input,
        l1_Wx, l1_bx, l1_Wh, l1_bh, l2_Wx, l2_bx, l2_Wh, l2_bh,
        fc1_W, fc1_b, fc2_W, fc2_b, fc3_W, fc3_b, (float*)d_out);
}

// round 16
// speedup vs baseline: 1.4829x; 1.0748x over previous
#include <cuda_runtime.h>
#include <cuda_fp16.h>
#include <math.h>
#include <stdint.h>

#define B_   256
#define T_   512
#define IN_  19
#define H_   512
#define KT1  9         // layer-1 chunks: 1 input + 8 hidden
#define KT2  16        // layer-2 chunks: 8 h1 + 8 h2
#define IMG  8192      // 64x64 fp16 swizzled image bytes (64 rows x 128B)
#define NCTA 128
#define NTHR 384
#define ABUF  8192                  // one A chunk
#define APIPE (3 * ABUF)            // 24 KB A pipeline
#define B1OFF APIPE                 // 9 x 8KB resident layer-1 weights
#define B2OFF (B1OFF + KT1 * IMG)   // 16 x 8KB resident layer-2 weights
#define SMEM_DYN (B2OFF + KT2 * IMG)   // 229376 B = 224 KB

// ---------------- static device scratch (no allocs allowed) ----------------
__device__ __align__(16) unsigned char g_Bim1[32][KT1][IMG];   // [jb][chunk]
__device__ __align__(16) unsigned char g_Bim2[32][KT2][IMG];
__device__ __align__(16) unsigned char g_Ain[T_][4][IMG];      // [t][mh]
__device__ __align__(16) unsigned char g_h1im[2][4][8][IMG];   // [slot][mh][jchunk]
__device__ __align__(16) unsigned char g_h2im[2][4][8][IMG];
__device__ float g_bias1[4 * H_], g_bias2[4 * H_];
__device__ float g_h2fin[B_][H_];
__device__ volatile unsigned g_count;      // global barrier (monotonic gen)
__device__ volatile unsigned g_gen;
__device__ volatile unsigned g_c1[4][2];   // [mh][band] L1-epilogue arrivals (2/CTA/interval)
__device__ volatile unsigned g_c2[4][2];   // [mh][band] L2-epilogue arrivals (2/CTA/interval)

// ---------------- helpers ---------------------------------------------------
__device__ __forceinline__ uint32_t swz_(uint32_t o) { return o ^ ((o >> 3) & 0x70); }

__device__ __forceinline__ __half2 tanh2_(__half2 x) {
    __half2 y;
    asm("tanh.approx.f16x2 %0, %1;" : "=r"(*(uint32_t*)&y) : "r"(*(const uint32_t*)&x));
    return y;
}
__device__ __forceinline__ __half2 sigm2_(__half2 x) {
    const __half2 hhalf = __float2half2_rn(0.5f);
    return __hfma2(tanh2_(__hmul2(x, hhalf)), hhalf, hhalf);
}

__device__ __forceinline__ uint32_t smem_u32_(const void* p) {
    uint32_t a;
    asm("{ .reg .u64 t; cvta.to.shared.u64 t, %1; cvt.u32.u64 %0, t; }" : "=r"(a) : "l"(p));
    return a;
}
__device__ __forceinline__ void ldsm4_(uint32_t* r, uint32_t a) {
    asm volatile("ldmatrix.sync.aligned.m8n8.x4.shared.b16 {%0,%1,%2,%3}, [%4];"
        : "=r"(r[0]), "=r"(r[1]), "=r"(r[2]), "=r"(r[3]) : "r"(a));
}
__device__ __forceinline__ void mma_(float* d, const uint32_t* a, const uint32_t* b) {
    asm volatile("mma.sync.aligned.m16n8k16.row.col.f32.f16.f16.f32 "
        "{%0,%1,%2,%3}, {%4,%5,%6,%7}, {%8,%9}, {%0,%1,%2,%3};"
        : "+f"(d[0]), "+f"(d[1]), "+f"(d[2]), "+f"(d[3])
        : "r"(a[0]), "r"(a[1]), "r"(a[2]), "r"(a[3]), "r"(b[0]), "r"(b[1]));
}
__device__ __forceinline__ void cpa_(uint32_t sa, const void* ga) {
    asm volatile("cp.async.cg.shared.global [%0], [%1], 16;" :: "r"(sa), "l"(ga));
}
__device__ __forceinline__ void pk8_(const float* v, uint32_t* out4) {
    #pragma unroll
    for (int q = 0; q < 4; q++) {
        unsigned short h0 = __half_as_ushort(__float2half_rn(v[2 * q]));
        unsigned short h1 = __half_as_ushort(__float2half_rn(v[2 * q + 1]));
        out4[q] = (uint32_t)h0 | ((uint32_t)h1 << 16);
    }
}

// ---------------- barriers ---------------------------------------------------
__device__ __forceinline__ void bar_any_(volatile unsigned* cnt, volatile unsigned* gen,
                                         unsigned n) {
    __syncthreads();
    if (threadIdx.x == 0) {
        __threadfence();
        unsigned g = *gen;
        if (atomicAdd((unsigned*)cnt, 1u) == n - 1u) {
            *cnt = 0;
            __threadfence();
            *gen = g + 1u;
        } else {
            while (*gen == g) { }
        }
        __threadfence();
    }
    __syncthreads();
}

__device__ __forceinline__ void wait_cnt_(volatile unsigned* c, unsigned tgt) {
    while (*c < tgt) { }
    __threadfence();
}

// ---------------- thin compute: 16 rows x 64 cols ----------------------------
__device__ __forceinline__ void compute_thin_(uint32_t abuf, uint32_t bimg,
    float acc[8][4], int l, int wtile, int nks)
{
    const uint32_t abyte = (uint32_t)(((l >> 4) & 1) * 16);
    const uint32_t brow0 = (uint32_t)(((l >> 4) & 1) * 8 + (l & 7));
    const uint32_t bbyte = (uint32_t)(((l >> 3) & 1) * 16);
    const uint32_t arow  = (uint32_t)(wtile * 16 + (l & 15));

    #pragma unroll
    for (int ks = 0; ks < 4; ks++) {
        if (ks >= nks) break;
        uint32_t a4[4];
        ldsm4_(a4, abuf + swz_(arow * 128 + (uint32_t)ks * 32 + abyte));
        #pragma unroll
        for (int tp = 0; tp < 4; tp++) {
            uint32_t b4[4];
            ldsm4_(b4, bimg + swz_(((uint32_t)tp * 16 + brow0) * 128 + (uint32_t)ks * 32 + bbyte));
            mma_(acc[2 * tp],     a4, b4);
            mma_(acc[2 * tp + 1], a4, b4 + 2);
        }
    }
}

// ---------------- fused LSTM cell epilogue (f16x2 MUFU path) -----------------
__device__ __forceinline__ void epilogue_(float acc[8][4], float* cst, const float* sb,
    int layer, int t, int mh, int jb, int w, int l, bool lastw)
{
    unsigned char* hb0 = (layer ? g_h2im : g_h1im)[(t + 1) & 1][mh][jb >> 2];

    #pragma unroll
    for (int a = 0; a < 2; a++) {
        #pragma unroll
        for (int rh = 0; rh < 2; rh++) {
            int row = 16 * w + (l >> 2) + rh * 8;
            int jj0 = 8 * a + 2 * (l & 3);
            float pi0 = acc[a][rh * 2 + 0]     + sb[jj0];
            float pi1 = acc[a][rh * 2 + 1]     + sb[jj0 + 1];
            float pf0 = acc[a + 2][rh * 2 + 0] + sb[16 + jj0];
            float pf1 = acc[a + 2][rh * 2 + 1] + sb[16 + jj0 + 1];
            float pg0 = acc[a + 4][rh * 2 + 0] + sb[32 + jj0];
            float pg1 = acc[a + 4][rh * 2 + 1] + sb[32 + jj0 + 1];
            float po0 = acc[a + 6][rh * 2 + 0] + sb[48 + jj0];
            float po1 = acc[a + 6][rh * 2 + 1] + sb[48 + jj0 + 1];

            __half2 si2 = sigm2_(__floats2half2_rn(pi0, pi1));
            __half2 sf2 = sigm2_(__floats2half2_rn(pf0, pf1));
            __half2 tg2 = tanh2_(__floats2half2_rn(pg0, pg1));
            __half2 so2 = sigm2_(__floats2half2_rn(po0, po1));

            float2 si = __half22float2(si2);
            float2 sf = __half22float2(sf2);
            float2 tg = __half22float2(tg2);

            int ci = a * 4 + rh * 2;
            float c0 = sf.x * cst[ci]     + si.x * tg.x;
            float c1 = sf.y * cst[ci + 1] + si.y * tg.y;
            cst[ci] = c0;
            cst[ci + 1] = c1;

            __half2 tc2 = tanh2_(__floats2half2_rn(c0, c1));
            __half2 h2v = __hmul2(so2, tc2);

            uint32_t off = swz_((uint32_t)(row * 128 + ((jb & 3) * 16 + jj0) * 2));
            *(uint32_t*)(hb0 + off) = *(const uint32_t*)&h2v;
            if (lastw) {
                float2 hf = __half22float2(h2v);
                g_h2fin[mh * 64 + row][jb * 16 + jj0]     = hf.x;
                g_h2fin[mh * 64 + row][jb * 16 + jj0 + 1] = hf.y;
            }
        }
    }
}

// ---------------- THE kernel ------------------------------------------------
// 128 CTAs x 384 threads, 1/SM (224KB smem). Weights smem-resident; A streams
// 17 x 8KB chunks (3-slot ring). Warp roles:
//   warps 0-7  = COMPUTE: (layer = w>>2, band = (w>>1)&1, mt = w&1),
//                16 rows x 64 cols each -> 2 compute warps per SMSP.
//   warps 8-11 = COPY: warp (8+2b+h) copies half h of band b's 4KB region.
// Per-band named barrier (id 1+band, 192 thr). Flow control by monotonic
// per-(mh,band) counters (2 arrivals/CTA/interval), arrive-early/wait-late.
__global__ void __launch_bounds__(NTHR, 1) lstm_all(
    const float* __restrict__ input,
    const float* __restrict__ l1_Wx, const float* __restrict__ l1_bx,
    const float* __restrict__ l1_Wh, const float* __restrict__ l1_bh,
    const float* __restrict__ l2_Wx, const float* __restrict__ l2_bx,
    const float* __restrict__ l2_Wh, const float* __restrict__ l2_bh,
    const float* __restrict__ fc1_W, const float* __restrict__ fc1_b,
    const float* __restrict__ fc2_W, const float* __restrict__ fc2_b,
    const float* __restrict__ fc3_W, const float* __restrict__ fc3_b,
    float* __restrict__ out)
{
    extern __shared__ unsigned char dsm[];
    __shared__ float s_bias[2][64];

    const int tid  = threadIdx.x;
    const int warp = tid >> 5;
    const int l    = tid & 31;
    const int mh   = blockIdx.x >> 5;   // 0..3
    const int jb   = blockIdx.x & 31;   // 0..31
    const uint32_t bufu = smem_u32_(dsm);

    const bool is_copy = (warp >= 8);
    const int band  = is_copy ? ((warp - 8) >> 1) : ((warp >> 1) & 1);
    const int half  = (warp - 8) & 1;               // copy only
    const int layer = warp >> 2;                    // compute: 0/1
    const int mt    = warp & 1;                     // compute only
    const int wtile = band * 2 + mt;                // row tile 0..3

    // ================= prep phase (distributed across grid) =================
    {
        const int gi = blockIdx.x * NTHR + tid;
        const int gs = NCTA * NTHR;

        if (blockIdx.x == 0 && tid < 16) {   // reset flow counters each launch
            if (tid < 8) ((volatile unsigned*)g_c1)[tid] = 0u;
            else         ((volatile unsigned*)g_c2)[tid - 8] = 0u;
        }

        for (int i = gi; i < 4 * H_; i += gs) {
            g_bias1[i] = l1_bx[i] + l1_bh[i];
            g_bias2[i] = l2_bx[i] + l2_bh[i];
        }
        {
            const int n16 = (4 * 8 * IMG) / 16;
            uint4 z = make_uint4(0, 0, 0, 0);
            uint4* p1 = (uint4*)&g_h1im[0][0][0][0];
            uint4* p2 = (uint4*)&g_h2im[0][0][0][0];
            for (int i = gi; i < n16; i += gs) { p1[i] = z; p2[i] = z; }
        }
        for (int e = gi; e < 32 * KT1 * 64 * 8; e += gs) {
            int k8 = e & 7, nrow = (e >> 3) & 63, c = (e >> 9) % KT1, jbx = (e >> 9) / KT1;
            int R = (nrow >> 4) * H_ + jbx * 16 + (nrow & 15);
            float v[8];
            #pragma unroll
            for (int q = 0; q < 8; q++) {
                int k = k8 * 8 + q;
                v[q] = (c == 0) ? ((k < IN_) ? l1_Wx[R * IN_ + k] : 0.0f)
                                : l1_Wh[R * H_ + (c - 1) * 64 + k];
            }
            uint32_t u4[4];
            pk8_(v, u4);
            *(uint4*)&g_Bim1[jbx][c][swz_((uint32_t)(nrow * 128 + k8 * 16))] =
                make_uint4(u4[0], u4[1], u4[2], u4[3]);
        }
        for (int e = gi; e < 32 * KT2 * 64 * 8; e += gs) {
            int k8 = e & 7, nrow = (e >> 3) & 63, c = (e >> 9) & 15, jbx = e >> 13;
            int R = (nrow >> 4) * H_ + jbx * 16 + (nrow & 15);
            float v[8];
            #pragma unroll
            for (int q = 0; q < 8; q++)
                v[q] = (c < 8) ? l2_Wx[R * H_ + c * 64 + k8 * 8 + q]
                               : l2_Wh[R * H_ + (c - 8) * 64 + k8 * 8 + q];
            uint32_t u4[4];
            pk8_(v, u4);
            *(uint4*)&g_Bim2[jbx][c][swz_((uint32_t)(nrow * 128 + k8 * 16))] =
                make_uint4(u4[0], u4[1], u4[2], u4[3]);
        }
        for (int e = gi; e < T_ * 4 * 64 * 8; e += gs) {
            int k8 = e & 7, r = (e >> 3) & 63, mhh = (e >> 9) & 3, t = e >> 11;
            int b = mhh * 64 + r;
            float v[8];
            #pragma unroll
            for (int q = 0; q < 8; q++) {
                int k = k8 * 8 + q;
                v[q] = (k < IN_) ? input[(size_t)b * (T_ * IN_) + t * IN_ + k] : 0.0f;
            }
            uint32_t u4[4];
            pk8_(v, u4);
            *(uint4*)&g_Ain[t][mhh][swz_((uint32_t)(r * 128 + k8 * 16))] =
                make_uint4(u4[0], u4[1], u4[2], u4[3]);
        }
    }
    bar_any_(&g_count, &g_gen, NCTA);   // prep + counter reset visible everywhere

    // ---- load resident weights into smem (once per launch) ----
    {
        for (int img = 0; img < KT1 + KT2; img++) {
            const uint4* src = (img < KT1) ? (const uint4*)g_Bim1[jb][img]
                                           : (const uint4*)g_Bim2[jb][img - KT1];
            uint32_t dst = bufu + B1OFF + (uint32_t)img * IMG;
            for (int e = tid; e < 512; e += NTHR)
                cpa_(dst + (uint32_t)e * 16, src + e);
        }
        asm volatile("cp.async.commit_group;" ::: "memory");
        asm volatile("cp.async.wait_group 0;" ::: "memory");
    }
    if (tid < 128) {
        int ly = tid >> 6, i = tid & 63;
        const float* bsrc = ly ? g_bias2 : g_bias1;
        s_bias[ly][i] = bsrc[(i >> 4) * H_ + jb * 16 + (i & 15)];
    }
    __syncthreads();

    // ================= persistent recurrence =================
    float cst[8];
    #pragma unroll
    for (int i = 0; i < 8; i++) cst[i] = 0.0f;

    for (int s = 0; s <= T_; s++) {
        const bool hasL1 = (s < T_), hasL2 = (s >= 1);
        const int c0 = hasL1 ? 0 : 1;
        const int c1 = hasL2 ? 17 : 9;

        auto asrc = [&](int i) -> const unsigned char* {
            if (i == 0)      return g_Ain[s][mh];
            else if (i < 9)  return g_h1im[s & 1][mh][i - 1];
            else             return g_h2im[(s - 1) & 1][mh][i - 9];
        };

        if (is_copy) {
            // ---- copy warp: owns 2KB of band's 4KB region ----
            const uint32_t roff = (uint32_t)(band * 4096 + half * 2048 + l * 16);
            auto issue = [&](int i) {
                const unsigned char* src = asrc(i) + roff;
                uint32_t dst = bufu + (uint32_t)(i % 3) * ABUF + roff;
                #pragma unroll
                for (int q = 0; q < 4; q++)
                    cpa_(dst + (uint32_t)q * 512u, src + q * 512);
                asm volatile("cp.async.commit_group;" ::: "memory");
            };
            if (c0 == 0) {
                issue(0);
                wait_cnt_(&g_c1[mh][band], 64u * (unsigned)s);
                issue(1);
            } else {   // s == T_: streams start at 1 (h1)
                wait_cnt_(&g_c1[mh][band], 64u * (unsigned)s);
                issue(1);
                issue(2);
            }
            for (int i = c0; i < c1; i++) {
                if (i < c1 - 1) asm volatile("cp.async.wait_group 1;" ::: "memory");
                else            asm volatile("cp.async.wait_group 0;" ::: "memory");
                asm volatile("bar.sync %0, 192;" :: "r"(1 + band) : "memory");
                if (i + 2 < c1) {
                    if (i + 2 == 9)   // first h2 stream: gate on L2 producers
                        wait_cnt_(&g_c2[mh][band], 64u * (unsigned)(s - 1));
                    issue(i + 2);
                }
            }
        } else {
            // ---- compute warp: (layer, band, mt), 16 rows x 64 cols ----
            float acc[8][4];
            for (int i = c0; i < c1; i++) {
                asm volatile("bar.sync %0, 192;" :: "r"(1 + band) : "memory");
                const uint32_t abuf = bufu + (uint32_t)(i % 3) * ABUF;

                if (layer == 0) {
                    if (hasL1 && i < 9) {
                        if (i == c0) {
                            #pragma unroll
                            for (int nt = 0; nt < 8; nt++)
                                #pragma unroll
                                for (int r = 0; r < 4; r++) acc[nt][r] = 0.0f;
                        }
                        compute_thin_(abuf, bufu + B1OFF + (uint32_t)i * IMG, acc, l, wtile,
                                      (i == 0) ? 2 : 4);
                        if (i == 8) {
                            epilogue_(acc, cst, s_bias[0], 0, s, mh, jb, wtile, l, false);
                            __threadfence();
                            __syncwarp();
                            if (l == 0) atomicAdd((unsigned*)&g_c1[mh][band], 1u);
                        }
                    }
                } else {
                    if (hasL2 && i >= 1) {
                        if (i == 1) {
                            #pragma unroll
                            for (int nt = 0; nt < 8; nt++)
                                #pragma unroll
                                for (int r = 0; r < 4; r++) acc[nt][r] = 0.0f;
                        }
                        compute_thin_(abuf, bufu + B2OFF + (uint32_t)(i - 1) * IMG, acc, l, wtile, 4);
                        if (i == 16) {
                            epilogue_(acc, cst, s_bias[1], 1, s - 1, mh, jb, wtile, l,
                                      (s - 1) == T_ - 1);
                            __threadfence();
                            __syncwarp();
                            if (l == 0) atomicAdd((unsigned*)&g_c2[mh][band], 1u);
                        }
                    }
                }
            }
        }
    }

    bar_any_(&g_count, &g_gen, NCTA);   // all flows done -> head

    // ================= FC head (blocks 0..31, 8 batches each) ================
    if (blockIdx.x < 32) {
        float* hv = (float*)dsm;             // [8][512]
        float* o1 = hv + 8 * 512;            // [8][256]
        float* o2 = o1 + 8 * 256;            // [8][128]
        const int b0 = blockIdx.x * 8;

        for (int i = tid; i < 8 * 512; i += NTHR)
            hv[i] = g_h2fin[b0 + (i >> 9)][i & 511];
        __syncthreads();

        if (tid < 256) {
            float acc[8] = {};
            const float* wp = &fc1_W[tid * 512];
            for (int k = 0; k < 512; k++) {
                float wv = wp[k];
                #pragma unroll
                for (int q = 0; q < 8; q++) acc[q] += wv * hv[q * 512 + k];
            }
            float bb = fc1_b[tid];
            #pragma unroll
            for (int q = 0; q < 8; q++) o1[q * 256 + tid] = fmaxf(acc[q] + bb, 0.0f);
        }
        __syncthreads();

        if (tid < 128) {
            float acc[8] = {};
            const float* wp = &fc2_W[tid * 256];
            for (int k = 0; k < 256; k++) {
                float wv = wp[k];
                #pragma unroll
                for (int q = 0; q < 8; q++) acc[q] += wv * o1[q * 256 + k];
            }
            float bb = fc2_b[tid];
            #pragma unroll
            for (int q = 0; q < 8; q++) o2[q * 128 + tid] = fmaxf(acc[q] + bb, 0.0f);
        }
        __syncthreads();

        if (tid < 8) {
            float sacc = 0.0f;
            for (int k = 0; k < 128; k++) sacc += fc3_W[k] * o2[tid * 128 + k];
            out[b0 + tid] = sacc + fc3_b[0];
        }
    }
}

// ---------------- launch -----------------------------------------------------
extern "C" void kernel_launch(void* const* d_in, const int* in_sizes, int n_in,
                              void* d_out, int out_size)
{
    const float* input  = (const float*)d_in[0];
    const float* l1_Wx  = (const float*)d_in[1];
    const float* l1_bx  = (const float*)d_in[2];
    const float* l1_Wh  = (const float*)d_in[3];
    const float* l1_bh  = (const float*)d_in[4];
    const float* l2_Wx  = (const float*)d_in[5];
    const float* l2_bx  = (const float*)d_in[6];
    const float* l2_Wh  = (const float*)d_in[7];
    const float* l2_bh  = (const float*)d_in[8];
    const float* fc1_W  = (const float*)d_in[9];
    const float* fc1_b  = (const float*)d_in[10];
    const float* fc2_W  = (const float*)d_in[11];
    const float* fc2_b  = (const float*)d_in[12];
    const float* fc3_W  = (const float*)d_in[13];
    const float* fc3_b  = (const float*)d_in[14];

    cudaFuncSetAttribute(lstm_all,
                         cudaFuncAttributeMaxDynamicSharedMemorySize, SMEM_DYN);

    lstm_all<<<NCTA, NTHR, SMEM_DYN>>>(input,
        l1_Wx, l1_bx, l1_Wh, l1_bh, l2_Wx, l2_bx, l2_Wh, l2_bh,
        fc1_W, fc1_b, fc2_W, fc2_b, fc3_W, fc3_b, (float*)d_out);
}